// round 1
// baseline (speedup 1.0000x reference)
#include <cuda_runtime.h>
#include <cstdint>

// Problem constants (fixed by the dataset)
constexpr int NN  = 100000;   // nodes
constexpr int NE  = 600000;   // edges
constexpr int DIM = 128;      // node feature dim
constexpr int EDIM = 64;      // edge feature dim
constexpr float RMS_EPS = 1.1920929e-07f;

// Scratch (device globals — no allocation allowed)
__device__ float g_agg[(size_t)NN * DIM];   // 51.2 MB
__device__ float g_deg[NN];
__device__ float g_inv[NN];

typedef unsigned long long ull;

// ---------- packed f32x2 helpers (sm_100+) ----------
__device__ __forceinline__ ull pack2(float a, float b) {
    ull r; asm("mov.b64 %0, {%1, %2};" : "=l"(r) : "f"(a), "f"(b)); return r;
}
__device__ __forceinline__ float2 unpack2(ull v) {
    float2 r; asm("mov.b64 {%0, %1}, %2;" : "=f"(r.x), "=f"(r.y) : "l"(v)); return r;
}
__device__ __forceinline__ void ffma2(ull &c, ull a, ull b) {
    asm("fma.rn.f32x2 %0, %1, %2, %0;" : "+l"(c) : "l"(a), "l"(b));
}

// ---------- small kernels ----------
__global__ void k_zero() {
    int i = blockIdx.x * blockDim.x + threadIdx.x;
    constexpr int n4 = NN * DIM / 4;  // 3,200,000
    if (i < n4) ((float4*)g_agg)[i] = make_float4(0.f, 0.f, 0.f, 0.f);
    if (i < NN) g_deg[i] = 0.f;
}

__global__ void k_deg(const int* __restrict__ dst) {
    int e = blockIdx.x * blockDim.x + threadIdx.x;
    if (e < NE) atomicAdd(&g_deg[dst[e]], 1.0f);
}

__global__ void k_inv() {
    int i = blockIdx.x * blockDim.x + threadIdx.x;
    if (i < NN) g_inv[i] = rsqrtf(fmaxf(g_deg[i], 1.0f));
}

// ---------- fused edge kernel ----------
// Per CTA: 128 edges. SMEM: attr tile (transposed), W1e, W2e, H tile (transposed).
// Each thread: 8 rows x 8 cols register tile (as 4 f32x2 col-pairs).
constexpr int ETM = 128;     // edges per block
constexpr int AS  = 132;     // attr_s row stride (pad to dodge alignment issues)
constexpr int HS  = 132;     // H_s row stride

__global__ void __launch_bounds__(256, 1) k_edge(
    const float* __restrict__ x,
    const int*   __restrict__ eidx,    // [2*NE]: src then dst
    const float* __restrict__ attr,
    const float* __restrict__ W1e, const float* __restrict__ b1e,
    const float* __restrict__ W2e, const float* __restrict__ b2e)
{
    extern __shared__ float sm[];
    float* attr_s = sm;                       // EDIM * AS
    float* W1s    = attr_s + EDIM * AS;       // EDIM * DIM
    float* W2s    = W1s + EDIM * DIM;         // DIM * DIM
    float* Hs     = W2s + DIM * DIM;          // DIM * HS
    float* b1s    = Hs + DIM * HS;            // DIM
    float* b2s    = b1s + DIM;                // DIM

    const int tid = threadIdx.x;
    const int e0  = blockIdx.x * ETM;
    const int* src = eidx;
    const int* dst = eidx + NE;

    // Load weights into SMEM
    #pragma unroll
    for (int it = 0; it < 8; ++it) {
        int idx = tid + it * 256;
        ((float4*)W1s)[idx] = ((const float4*)W1e)[idx];
    }
    #pragma unroll
    for (int it = 0; it < 16; ++it) {
        int idx = tid + it * 256;
        ((float4*)W2s)[idx] = ((const float4*)W2e)[idx];
    }
    if (tid < DIM) { b1s[tid] = b1e[tid]; b2s[tid] = b2e[tid]; }

    // Load attr tile, transposed: attr_s[k][row]
    #pragma unroll
    for (int it = 0; it < 8; ++it) {
        int idx = tid + it * 256;          // 0..2047
        int row = idx >> 4;                // 0..127
        int kq  = (idx & 15) << 2;         // 0..60
        int e = e0 + row; if (e >= NE) e = NE - 1;
        float4 v = *(const float4*)(attr + (size_t)e * EDIM + kq);
        attr_s[(kq + 0) * AS + row] = v.x;
        attr_s[(kq + 1) * AS + row] = v.y;
        attr_s[(kq + 2) * AS + row] = v.z;
        attr_s[(kq + 3) * AS + row] = v.w;
    }
    __syncthreads();

    const int tc = tid & 15;  const int c0 = tc * 8;
    const int tr = tid >> 4;  const int r0 = tr * 8;

    ull acc[8][4];
    #pragma unroll
    for (int r = 0; r < 8; ++r)
        #pragma unroll
        for (int p = 0; p < 4; ++p) acc[r][p] = 0ull;

    // GEMM1: H = relu(attr @ W1e + b1e), K = 64
    #pragma unroll 4
    for (int k = 0; k < EDIM; ++k) {
        float4 a0 = *(float4*)&attr_s[k * AS + r0];
        float4 a1 = *(float4*)&attr_s[k * AS + r0 + 4];
        float4 w0 = *(float4*)&W1s[k * DIM + c0];
        float4 w1 = *(float4*)&W1s[k * DIM + c0 + 4];
        ull wp0 = pack2(w0.x, w0.y), wp1 = pack2(w0.z, w0.w);
        ull wp2 = pack2(w1.x, w1.y), wp3 = pack2(w1.z, w1.w);
        float ar[8] = {a0.x, a0.y, a0.z, a0.w, a1.x, a1.y, a1.z, a1.w};
        #pragma unroll
        for (int r = 0; r < 8; ++r) {
            ull ap = pack2(ar[r], ar[r]);
            ffma2(acc[r][0], ap, wp0);
            ffma2(acc[r][1], ap, wp1);
            ffma2(acc[r][2], ap, wp2);
            ffma2(acc[r][3], ap, wp3);
        }
    }

    // bias + relu -> Hs[j][row] (transposed)
    #pragma unroll
    for (int p = 0; p < 4; ++p) {
        float2 v0 = unpack2(acc[0][p]), v1 = unpack2(acc[1][p]);
        float2 v2 = unpack2(acc[2][p]), v3 = unpack2(acc[3][p]);
        float2 v4 = unpack2(acc[4][p]), v5 = unpack2(acc[5][p]);
        float2 v6 = unpack2(acc[6][p]), v7 = unpack2(acc[7][p]);
        int j0 = c0 + 2 * p;
        float bj0 = b1s[j0], bj1 = b1s[j0 + 1];
        float4 A = make_float4(fmaxf(v0.x + bj0, 0.f), fmaxf(v1.x + bj0, 0.f),
                               fmaxf(v2.x + bj0, 0.f), fmaxf(v3.x + bj0, 0.f));
        float4 B = make_float4(fmaxf(v4.x + bj0, 0.f), fmaxf(v5.x + bj0, 0.f),
                               fmaxf(v6.x + bj0, 0.f), fmaxf(v7.x + bj0, 0.f));
        float4 C = make_float4(fmaxf(v0.y + bj1, 0.f), fmaxf(v1.y + bj1, 0.f),
                               fmaxf(v2.y + bj1, 0.f), fmaxf(v3.y + bj1, 0.f));
        float4 Dv = make_float4(fmaxf(v4.y + bj1, 0.f), fmaxf(v5.y + bj1, 0.f),
                                fmaxf(v6.y + bj1, 0.f), fmaxf(v7.y + bj1, 0.f));
        *(float4*)&Hs[j0 * HS + r0]           = A;
        *(float4*)&Hs[j0 * HS + r0 + 4]       = B;
        *(float4*)&Hs[(j0 + 1) * HS + r0]     = C;
        *(float4*)&Hs[(j0 + 1) * HS + r0 + 4] = Dv;
    }
    __syncthreads();

    // GEMM2: M = H @ W2e, K = 128
    #pragma unroll
    for (int r = 0; r < 8; ++r)
        #pragma unroll
        for (int p = 0; p < 4; ++p) acc[r][p] = 0ull;

    #pragma unroll 4
    for (int k = 0; k < DIM; ++k) {
        float4 a0 = *(float4*)&Hs[k * HS + r0];
        float4 a1 = *(float4*)&Hs[k * HS + r0 + 4];
        float4 w0 = *(float4*)&W2s[k * DIM + c0];
        float4 w1 = *(float4*)&W2s[k * DIM + c0 + 4];
        ull wp0 = pack2(w0.x, w0.y), wp1 = pack2(w0.z, w0.w);
        ull wp2 = pack2(w1.x, w1.y), wp3 = pack2(w1.z, w1.w);
        float ar[8] = {a0.x, a0.y, a0.z, a0.w, a1.x, a1.y, a1.z, a1.w};
        #pragma unroll
        for (int r = 0; r < 8; ++r) {
            ull ap = pack2(ar[r], ar[r]);
            ffma2(acc[r][0], ap, wp0);
            ffma2(acc[r][1], ap, wp1);
            ffma2(acc[r][2], ap, wp2);
            ffma2(acc[r][3], ap, wp3);
        }
    }

    // Epilogue: message = (x[src] + M + b2e) * w; atomic scatter into agg[dst]
    float b2v[8];
    #pragma unroll
    for (int j = 0; j < 8; ++j) b2v[j] = b2s[c0 + j];

    #pragma unroll
    for (int r = 0; r < 8; ++r) {
        int e = e0 + r0 + r;
        bool valid = (e < NE);
        int ec = valid ? e : 0;
        int s  = src[ec];
        int dn = dst[ec];
        float w = g_inv[s] * g_inv[dn];
        const float4* xp = (const float4*)(x + (size_t)s * DIM + c0);
        float4 x0 = xp[0], x1 = xp[1];
        float2 m0 = unpack2(acc[r][0]), m1 = unpack2(acc[r][1]);
        float2 m2 = unpack2(acc[r][2]), m3 = unpack2(acc[r][3]);
        float4 o0 = make_float4((m0.x + b2v[0] + x0.x) * w, (m0.y + b2v[1] + x0.y) * w,
                                (m1.x + b2v[2] + x0.z) * w, (m1.y + b2v[3] + x0.w) * w);
        float4 o1 = make_float4((m2.x + b2v[4] + x1.x) * w, (m2.y + b2v[5] + x1.y) * w,
                                (m3.x + b2v[6] + x1.z) * w, (m3.y + b2v[7] + x1.w) * w);
        if (valid) {
            atomicAdd((float4*)(g_agg + (size_t)dn * DIM + c0), o0);
            atomicAdd((float4*)(g_agg + (size_t)dn * DIM + c0 + 4), o1);
        }
    }
}

// ---------- fused node kernel ----------
// Per CTA: 64 nodes. combined -> MLP -> residual -> RMSNorm.
constexpr int NTM = 64;
constexpr int CS  = 68;    // comb/H row stride

__global__ void __launch_bounds__(256, 1) k_node(
    const float* __restrict__ x,
    const float* __restrict__ W1n, const float* __restrict__ b1n,
    const float* __restrict__ W2n, const float* __restrict__ b2n,
    const float* __restrict__ gin_eps, const float* __restrict__ rms_w,
    float* __restrict__ out)
{
    extern __shared__ float sm[];
    float* Cs  = sm;                    // DIM * CS
    float* W1s = Cs + DIM * CS;         // DIM * DIM
    float* W2s = W1s + DIM * DIM;       // DIM * DIM
    float* Hs  = W2s + DIM * DIM;       // DIM * CS
    float* b1s = Hs + DIM * CS;
    float* b2s = b1s + DIM;
    float* rws = b2s + DIM;

    const int tid = threadIdx.x;
    const int n0  = blockIdx.x * NTM;
    const float epsv = gin_eps[0];

    #pragma unroll
    for (int it = 0; it < 16; ++it) {
        int idx = tid + it * 256;
        ((float4*)W1s)[idx] = ((const float4*)W1n)[idx];
        ((float4*)W2s)[idx] = ((const float4*)W2n)[idx];
    }
    if (tid < DIM) { b1s[tid] = b1n[tid]; b2s[tid] = b2n[tid]; rws[tid] = rms_w[tid]; }

    // combined = (1+eps)*x + agg, transposed into Cs[k][row]
    #pragma unroll
    for (int it = 0; it < 8; ++it) {
        int idx = tid + it * 256;          // 0..2047
        int row = idx >> 5;                // 0..63
        int kq  = (idx & 31) << 2;         // 0..124
        int nn = n0 + row; int nc = (nn < NN) ? nn : NN - 1;
        float4 xv = *(const float4*)(x + (size_t)nc * DIM + kq);
        float4 av = *(const float4*)(g_agg + (size_t)nc * DIM + kq);
        float f = 1.f + epsv;
        Cs[(kq + 0) * CS + row] = f * xv.x + av.x;
        Cs[(kq + 1) * CS + row] = f * xv.y + av.y;
        Cs[(kq + 2) * CS + row] = f * xv.z + av.z;
        Cs[(kq + 3) * CS + row] = f * xv.w + av.w;
    }
    __syncthreads();

    const int tc = tid & 15;  const int c0 = tc * 8;
    const int tr = tid >> 4;  const int r0 = tr * 4;

    ull acc[4][4];
    #pragma unroll
    for (int r = 0; r < 4; ++r)
        #pragma unroll
        for (int p = 0; p < 4; ++p) acc[r][p] = 0ull;

    // GEMM1: H = relu(comb @ W1n + b1n)
    #pragma unroll 4
    for (int k = 0; k < DIM; ++k) {
        float4 a = *(float4*)&Cs[k * CS + r0];
        float4 w0 = *(float4*)&W1s[k * DIM + c0];
        float4 w1 = *(float4*)&W1s[k * DIM + c0 + 4];
        ull wp0 = pack2(w0.x, w0.y), wp1 = pack2(w0.z, w0.w);
        ull wp2 = pack2(w1.x, w1.y), wp3 = pack2(w1.z, w1.w);
        float ar[4] = {a.x, a.y, a.z, a.w};
        #pragma unroll
        for (int r = 0; r < 4; ++r) {
            ull ap = pack2(ar[r], ar[r]);
            ffma2(acc[r][0], ap, wp0);
            ffma2(acc[r][1], ap, wp1);
            ffma2(acc[r][2], ap, wp2);
            ffma2(acc[r][3], ap, wp3);
        }
    }

    #pragma unroll
    for (int p = 0; p < 4; ++p) {
        float2 v0 = unpack2(acc[0][p]), v1 = unpack2(acc[1][p]);
        float2 v2 = unpack2(acc[2][p]), v3 = unpack2(acc[3][p]);
        int j0 = c0 + 2 * p;
        float bj0 = b1s[j0], bj1 = b1s[j0 + 1];
        float4 A = make_float4(fmaxf(v0.x + bj0, 0.f), fmaxf(v1.x + bj0, 0.f),
                               fmaxf(v2.x + bj0, 0.f), fmaxf(v3.x + bj0, 0.f));
        float4 B = make_float4(fmaxf(v0.y + bj1, 0.f), fmaxf(v1.y + bj1, 0.f),
                               fmaxf(v2.y + bj1, 0.f), fmaxf(v3.y + bj1, 0.f));
        *(float4*)&Hs[j0 * CS + r0]       = A;
        *(float4*)&Hs[(j0 + 1) * CS + r0] = B;
    }
    __syncthreads();

    #pragma unroll
    for (int r = 0; r < 4; ++r)
        #pragma unroll
        for (int p = 0; p < 4; ++p) acc[r][p] = 0ull;

    // GEMM2: out = H @ W2n
    #pragma unroll 4
    for (int k = 0; k < DIM; ++k) {
        float4 a = *(float4*)&Hs[k * CS + r0];
        float4 w0 = *(float4*)&W2s[k * DIM + c0];
        float4 w1 = *(float4*)&W2s[k * DIM + c0 + 4];
        ull wp0 = pack2(w0.x, w0.y), wp1 = pack2(w0.z, w0.w);
        ull wp2 = pack2(w1.x, w1.y), wp3 = pack2(w1.z, w1.w);
        float ar[4] = {a.x, a.y, a.z, a.w};
        #pragma unroll
        for (int r = 0; r < 4; ++r) {
            ull ap = pack2(ar[r], ar[r]);
            ffma2(acc[r][0], ap, wp0);
            ffma2(acc[r][1], ap, wp1);
            ffma2(acc[r][2], ap, wp2);
            ffma2(acc[r][3], ap, wp3);
        }
    }

    // Epilogue: + b2n + x residual, RMSNorm (reduce across 16 lanes), store
    float b2v[8], rw[8];
    #pragma unroll
    for (int j = 0; j < 8; ++j) { b2v[j] = b2s[c0 + j]; rw[j] = rws[c0 + j]; }

    #pragma unroll
    for (int r = 0; r < 4; ++r) {
        int nn = n0 + r0 + r;
        bool valid = (nn < NN);
        int nc = valid ? nn : NN - 1;
        const float4* xp = (const float4*)(x + (size_t)nc * DIM + c0);
        float4 x0 = xp[0], x1 = xp[1];
        float2 m0 = unpack2(acc[r][0]), m1 = unpack2(acc[r][1]);
        float2 m2 = unpack2(acc[r][2]), m3 = unpack2(acc[r][3]);
        float o[8];
        o[0] = m0.x + b2v[0] + x0.x;  o[1] = m0.y + b2v[1] + x0.y;
        o[2] = m1.x + b2v[2] + x0.z;  o[3] = m1.y + b2v[3] + x0.w;
        o[4] = m2.x + b2v[4] + x1.x;  o[5] = m2.y + b2v[5] + x1.y;
        o[6] = m3.x + b2v[6] + x1.z;  o[7] = m3.y + b2v[7] + x1.w;
        float ss = 0.f;
        #pragma unroll
        for (int j = 0; j < 8; ++j) ss += o[j] * o[j];
        ss += __shfl_xor_sync(0xFFFFFFFFu, ss, 1);
        ss += __shfl_xor_sync(0xFFFFFFFFu, ss, 2);
        ss += __shfl_xor_sync(0xFFFFFFFFu, ss, 4);
        ss += __shfl_xor_sync(0xFFFFFFFFu, ss, 8);
        float sc = rsqrtf(ss * (1.f / 128.f) + RMS_EPS);
        if (valid) {
            float4 O0 = make_float4(o[0] * sc * rw[0], o[1] * sc * rw[1],
                                    o[2] * sc * rw[2], o[3] * sc * rw[3]);
            float4 O1 = make_float4(o[4] * sc * rw[4], o[5] * sc * rw[5],
                                    o[6] * sc * rw[6], o[7] * sc * rw[7]);
            *(float4*)(out + (size_t)nn * DIM + c0)     = O0;
            *(float4*)(out + (size_t)nn * DIM + c0 + 4) = O1;
        }
    }
}

// ---------- launch ----------
extern "C" void kernel_launch(void* const* d_in, const int* in_sizes, int n_in,
                              void* d_out, int out_size)
{
    const float* x    = (const float*)d_in[0];
    const int*   eidx = (const int*)  d_in[1];
    const float* attr = (const float*)d_in[2];
    const float* W1n  = (const float*)d_in[3];
    const float* b1n  = (const float*)d_in[4];
    const float* W2n  = (const float*)d_in[5];
    const float* b2n  = (const float*)d_in[6];
    const float* W1e  = (const float*)d_in[7];
    const float* b1e  = (const float*)d_in[8];
    const float* W2e  = (const float*)d_in[9];
    const float* b2e  = (const float*)d_in[10];
    const float* geps = (const float*)d_in[11];
    const float* rmsw = (const float*)d_in[12];
    float* out = (float*)d_out;

    size_t smem_e = (size_t)(EDIM * AS + EDIM * DIM + DIM * DIM + DIM * HS + 2 * DIM) * sizeof(float);
    size_t smem_n = (size_t)(DIM * CS + 2 * DIM * DIM + DIM * CS + 3 * DIM) * sizeof(float);
    cudaFuncSetAttribute(k_edge, cudaFuncAttributeMaxDynamicSharedMemorySize, (int)smem_e);
    cudaFuncSetAttribute(k_node, cudaFuncAttributeMaxDynamicSharedMemorySize, (int)smem_n);

    k_zero<<<(NN * DIM / 4 + 255) / 256, 256>>>();
    k_deg<<<(NE + 255) / 256, 256>>>(eidx + NE);
    k_inv<<<(NN + 255) / 256, 256>>>();
    k_edge<<<(NE + ETM - 1) / ETM, 256, smem_e>>>(x, eidx, attr, W1e, b1e, W2e, b2e);
    k_node<<<(NN + NTM - 1) / NTM, 256, smem_n>>>(x, W1n, b1n, W2n, b2n, geps, rmsw, out);
}

// round 4
// speedup vs baseline: 1.7632x; 1.7632x over previous
#include <cuda_runtime.h>
#include <cstdint>

typedef unsigned int u32;

// Problem constants
constexpr int NN  = 100000;
constexpr int NE  = 600000;
constexpr int DIM = 128;
constexpr int EDIM = 64;
constexpr float RMS_EPS = 1.1920929e-07f;

constexpr int SA = 68;    // stride (floats) for K=64 tiles (attr, W1e)
constexpr int SH = 132;   // stride (floats) for K=128 tiles (H, W2, C, W1n, W2n)

// Scratch (device globals)
__device__ float g_agg[(size_t)NN * DIM];
__device__ float g_deg[NN];
__device__ float g_inv[NN];
// Transposed, padded, tf32-rounded weight images: [n][k] row-major
__device__ float g_iW1e[128 * SA];
__device__ float g_iW2e[128 * SH];
__device__ float g_iW1n[128 * SH];
__device__ float g_iW2n[128 * SH];

// ---------------- helpers ----------------
__device__ __forceinline__ u32 to_tf32(float v) {
    u32 r; asm("cvt.rna.tf32.f32 %0, %1;" : "=r"(r) : "f"(v)); return r;
}
__device__ __forceinline__ void mma_tf32(float* c, const u32* a, const u32* b) {
    asm volatile("mma.sync.aligned.m16n8k8.row.col.f32.tf32.tf32.f32 "
        "{%0,%1,%2,%3}, {%4,%5,%6,%7}, {%8,%9}, {%0,%1,%2,%3};"
        : "+f"(c[0]), "+f"(c[1]), "+f"(c[2]), "+f"(c[3])
        : "r"(a[0]), "r"(a[1]), "r"(a[2]), "r"(a[3]), "r"(b[0]), "r"(b[1]));
}

// ---------------- small kernels ----------------
__global__ void k_zero() {
    int i = blockIdx.x * blockDim.x + threadIdx.x;
    constexpr int n4 = NN * DIM / 4;
    if (i < n4) ((float4*)g_agg)[i] = make_float4(0.f, 0.f, 0.f, 0.f);
    if (i < NN) g_deg[i] = 0.f;
}
__global__ void k_deg(const int* __restrict__ dst) {
    int e = blockIdx.x * blockDim.x + threadIdx.x;
    if (e < NE) atomicAdd(&g_deg[dst[e]], 1.0f);
}
__global__ void k_inv() {
    int i = blockIdx.x * blockDim.x + threadIdx.x;
    if (i < NN) g_inv[i] = rsqrtf(fmaxf(g_deg[i], 1.0f));
}
// Build transposed+padded+tf32 weight images. Source W is [K,N] row-major.
__global__ void k_prep(const float* __restrict__ W1e, const float* __restrict__ W2e,
                       const float* __restrict__ W1n, const float* __restrict__ W2n) {
    int i = blockIdx.x * blockDim.x + threadIdx.x;
    if (i < 8192) {
        int k = i >> 7, n = i & 127;
        g_iW1e[n * SA + k] = __uint_as_float(to_tf32(W1e[i]));
    } else if (i < 24576) {
        int j = i - 8192; int k = j >> 7, n = j & 127;
        g_iW2e[n * SH + k] = __uint_as_float(to_tf32(W2e[j]));
    } else if (i < 40960) {
        int j = i - 24576; int k = j >> 7, n = j & 127;
        g_iW1n[n * SH + k] = __uint_as_float(to_tf32(W1n[j]));
    } else if (i < 57344) {
        int j = i - 40960; int k = j >> 7, n = j & 127;
        g_iW2n[n * SH + k] = __uint_as_float(to_tf32(W2n[j]));
    }
}

// ---------------- fused edge kernel (mma.sync tf32, persistent) ----------------
// SMEM floats: attr[128*SA] | W1[128*SA] | H/stage[128*SH] | W2[128*SH] | b1[128] b2[128]
constexpr int EF_ATTR = 0;
constexpr int EF_W1   = EF_ATTR + 128 * SA;
constexpr int EF_H    = EF_W1 + 128 * SA;
constexpr int EF_W2   = EF_H + 128 * SH;
constexpr int EF_B1   = EF_W2 + 128 * SH;
constexpr int EF_B2   = EF_B1 + 128;
constexpr int EF_TOT  = EF_B2 + 128;
constexpr int SME_EDGE = EF_TOT * 4;
constexpr int NT_E = (NE + 127) / 128;   // 4688 tiles

__global__ void __launch_bounds__(256, 1) k_edge(
    const float* __restrict__ x, const int* __restrict__ eidx,
    const float* __restrict__ attr,
    const float* __restrict__ b1e, const float* __restrict__ b2e)
{
    extern __shared__ float sm[];
    float* attr_s = sm + EF_ATTR;
    float* W1s    = sm + EF_W1;
    float* Hs     = sm + EF_H;
    float* W2s    = sm + EF_W2;
    float* b1s    = sm + EF_B1;
    float* b2s    = sm + EF_B2;

    const int tid = threadIdx.x, wid = tid >> 5, lid = tid & 31;
    const int rg = wid & 3, ch = wid >> 2;     // row group (x32), col half (x64)
    const int q = lid >> 2, m = lid & 3;
    const int* src = eidx;
    const int* dst = eidx + NE;

    // Load weights once (persistent)
    for (int i = tid; i < 128 * SA / 4; i += 256)
        ((float4*)W1s)[i] = ((const float4*)g_iW1e)[i];
    for (int i = tid; i < 128 * SH / 4; i += 256)
        ((float4*)W2s)[i] = ((const float4*)g_iW2e)[i];
    if (tid < 128) { b1s[tid] = b1e[tid]; b2s[tid] = b2e[tid]; }

    const u32* Au = (const u32*)attr_s;
    const u32* Hu = (const u32*)Hs;
    const u32* B1 = (const u32*)W1s;
    const u32* B2 = (const u32*)W2s;

    for (int t = blockIdx.x; t < NT_E; t += gridDim.x) {
        const int e0 = t * 128;
        __syncthreads();   // protect attr & stage from previous tile readers

        // Load attr tile [128 x 64] (tf32-rounded)
        #pragma unroll
        for (int it = 0; it < 8; ++it) {
            int idx = tid + it * 256;          // 0..2047
            int row = idx >> 4, k4 = (idx & 15) * 4;
            int e = e0 + row; if (e >= NE) e = NE - 1;
            float4 v = *(const float4*)(attr + (size_t)e * EDIM + k4);
            u32* p = (u32*)(attr_s + row * SA + k4);
            p[0] = to_tf32(v.x); p[1] = to_tf32(v.y);
            p[2] = to_tf32(v.z); p[3] = to_tf32(v.w);
        }
        __syncthreads();

        // GEMM1: H = attr @ W1e  (K=64), warp tile m32 x n64
        float acc[2][8][4];
        #pragma unroll
        for (int mg = 0; mg < 2; ++mg)
            #pragma unroll
            for (int j = 0; j < 8; ++j)
                #pragma unroll
                for (int c = 0; c < 4; ++c) acc[mg][j][c] = 0.f;

        #pragma unroll 2
        for (int kk = 0; kk < 8; ++kk) {
            int kb = kk * 8;
            u32 a[2][4];
            #pragma unroll
            for (int mg = 0; mg < 2; ++mg) {
                int r0 = 32 * rg + 16 * mg + q;
                a[mg][0] = Au[r0 * SA + kb + m];
                a[mg][1] = Au[(r0 + 8) * SA + kb + m];
                a[mg][2] = Au[r0 * SA + kb + m + 4];
                a[mg][3] = Au[(r0 + 8) * SA + kb + m + 4];
            }
            u32 b[8][2];
            #pragma unroll
            for (int j = 0; j < 8; ++j) {
                int n = 64 * ch + 8 * j + q;
                b[j][0] = B1[n * SA + kb + m];
                b[j][1] = B1[n * SA + kb + m + 4];
            }
            #pragma unroll
            for (int mg = 0; mg < 2; ++mg)
                #pragma unroll
                for (int j = 0; j < 8; ++j) mma_tf32(acc[mg][j], a[mg], b[j]);
        }

        // H = relu(acc + b1), tf32-rounded, into Hs
        #pragma unroll
        for (int mg = 0; mg < 2; ++mg) {
            int r0 = 32 * rg + 16 * mg + q;
            #pragma unroll
            for (int j = 0; j < 8; ++j) {
                int col = 64 * ch + 8 * j + 2 * m;
                float bj0 = b1s[col], bj1 = b1s[col + 1];
                u32* p0 = (u32*)(Hs + r0 * SH + col);
                u32* p1 = (u32*)(Hs + (r0 + 8) * SH + col);
                p0[0] = to_tf32(fmaxf(acc[mg][j][0] + bj0, 0.f));
                p0[1] = to_tf32(fmaxf(acc[mg][j][1] + bj1, 0.f));
                p1[0] = to_tf32(fmaxf(acc[mg][j][2] + bj0, 0.f));
                p1[1] = to_tf32(fmaxf(acc[mg][j][3] + bj1, 0.f));
            }
        }
        __syncthreads();

        // GEMM2: M = H @ W2e  (K=128)
        #pragma unroll
        for (int mg = 0; mg < 2; ++mg)
            #pragma unroll
            for (int j = 0; j < 8; ++j)
                #pragma unroll
                for (int c = 0; c < 4; ++c) acc[mg][j][c] = 0.f;

        #pragma unroll 2
        for (int kk = 0; kk < 16; ++kk) {
            int kb = kk * 8;
            u32 a[2][4];
            #pragma unroll
            for (int mg = 0; mg < 2; ++mg) {
                int r0 = 32 * rg + 16 * mg + q;
                a[mg][0] = Hu[r0 * SH + kb + m];
                a[mg][1] = Hu[(r0 + 8) * SH + kb + m];
                a[mg][2] = Hu[r0 * SH + kb + m + 4];
                a[mg][3] = Hu[(r0 + 8) * SH + kb + m + 4];
            }
            u32 b[8][2];
            #pragma unroll
            for (int j = 0; j < 8; ++j) {
                int n = 64 * ch + 8 * j + q;
                b[j][0] = B2[n * SH + kb + m];
                b[j][1] = B2[n * SH + kb + m + 4];
            }
            #pragma unroll
            for (int mg = 0; mg < 2; ++mg)
                #pragma unroll
                for (int j = 0; j < 8; ++j) mma_tf32(acc[mg][j], a[mg], b[j]);
        }
        __syncthreads();   // all H reads done; Hs becomes staging

        // Stage msg = acc + b2 into Hs
        #pragma unroll
        for (int mg = 0; mg < 2; ++mg) {
            int r0 = 32 * rg + 16 * mg + q;
            #pragma unroll
            for (int j = 0; j < 8; ++j) {
                int col = 64 * ch + 8 * j + 2 * m;
                float bj0 = b2s[col], bj1 = b2s[col + 1];
                Hs[r0 * SH + col]           = acc[mg][j][0] + bj0;
                Hs[r0 * SH + col + 1]       = acc[mg][j][1] + bj1;
                Hs[(r0 + 8) * SH + col]     = acc[mg][j][2] + bj0;
                Hs[(r0 + 8) * SH + col + 1] = acc[mg][j][3] + bj1;
            }
        }
        __syncthreads();

        // Epilogue: o = (x[src] + msg) * w; atomic scatter (warp = 1 row → coalesced)
        #pragma unroll
        for (int it = 0; it < 16; ++it) {
            int idx = tid + it * 256;       // 0..4095
            int row = idx >> 5, c4 = idx & 31;
            int e = e0 + row;
            if (e < NE) {
                int s = src[e], dn = dst[e];
                float w = g_inv[s] * g_inv[dn];
                float4 mv = *(float4*)(Hs + row * SH + c4 * 4);
                float4 xv = *(const float4*)(x + (size_t)s * DIM + c4 * 4);
                float4 o = make_float4((mv.x + xv.x) * w, (mv.y + xv.y) * w,
                                       (mv.z + xv.z) * w, (mv.w + xv.w) * w);
                atomicAdd((float4*)(g_agg + (size_t)dn * DIM + c4 * 4), o);
            }
        }
    }
}

// ---------------- fused node kernel (mma.sync tf32, persistent) ----------------
// SMEM floats: C/H/stage[128*SH] | W1n[128*SH] | W2n[128*SH] | b1 b2 rms [384] | ssb[256]
constexpr int NF_C  = 0;
constexpr int NF_W1 = NF_C + 128 * SH;
constexpr int NF_W2 = NF_W1 + 128 * SH;
constexpr int NF_B1 = NF_W2 + 128 * SH;
constexpr int NF_B2 = NF_B1 + 128;
constexpr int NF_RW = NF_B2 + 128;
constexpr int NF_SS = NF_RW + 128;
constexpr int NF_TOT = NF_SS + 256;
constexpr int SME_NODE = NF_TOT * 4;
constexpr int NT_N = (NN + 127) / 128;   // 782 tiles

__global__ void __launch_bounds__(256, 1) k_node(
    const float* __restrict__ x,
    const float* __restrict__ b1n, const float* __restrict__ b2n,
    const float* __restrict__ gin_eps, const float* __restrict__ rms_w,
    float* __restrict__ out)
{
    extern __shared__ float sm[];
    float* Cs  = sm + NF_C;     // also H, also staging
    float* W1s = sm + NF_W1;
    float* W2s = sm + NF_W2;
    float* b1s = sm + NF_B1;
    float* b2s = sm + NF_B2;
    float* rws = sm + NF_RW;
    float* ssb = sm + NF_SS;

    const int tid = threadIdx.x, wid = tid >> 5, lid = tid & 31;
    const int rg = wid & 3, ch = wid >> 2;
    const int q = lid >> 2, m = lid & 3;
    const float f = 1.f + gin_eps[0];

    for (int i = tid; i < 128 * SH / 4; i += 256) {
        ((float4*)W1s)[i] = ((const float4*)g_iW1n)[i];
        ((float4*)W2s)[i] = ((const float4*)g_iW2n)[i];
    }
    if (tid < 128) { b1s[tid] = b1n[tid]; b2s[tid] = b2n[tid]; rws[tid] = rms_w[tid]; }

    const u32* Cu = (const u32*)Cs;
    const u32* B1 = (const u32*)W1s;
    const u32* B2 = (const u32*)W2s;

    for (int t = blockIdx.x; t < NT_N; t += gridDim.x) {
        const int n0 = t * 128;
        __syncthreads();

        // C = (1+eps)*x + agg, tf32-rounded
        #pragma unroll
        for (int it = 0; it < 16; ++it) {
            int idx = tid + it * 256;
            int row = idx >> 5, c4 = (idx & 31) * 4;
            int nn = n0 + row; int nc = (nn < NN) ? nn : NN - 1;
            float4 xv = *(const float4*)(x + (size_t)nc * DIM + c4);
            float4 av = *(const float4*)(g_agg + (size_t)nc * DIM + c4);
            u32* p = (u32*)(Cs + row * SH + c4);
            p[0] = to_tf32(f * xv.x + av.x);
            p[1] = to_tf32(f * xv.y + av.y);
            p[2] = to_tf32(f * xv.z + av.z);
            p[3] = to_tf32(f * xv.w + av.w);
        }
        __syncthreads();

        // GEMM1: H = C @ W1n (K=128)
        float acc[2][8][4];
        #pragma unroll
        for (int mg = 0; mg < 2; ++mg)
            #pragma unroll
            for (int j = 0; j < 8; ++j)
                #pragma unroll
                for (int c = 0; c < 4; ++c) acc[mg][j][c] = 0.f;

        #pragma unroll 2
        for (int kk = 0; kk < 16; ++kk) {
            int kb = kk * 8;
            u32 a[2][4];
            #pragma unroll
            for (int mg = 0; mg < 2; ++mg) {
                int r0 = 32 * rg + 16 * mg + q;
                a[mg][0] = Cu[r0 * SH + kb + m];
                a[mg][1] = Cu[(r0 + 8) * SH + kb + m];
                a[mg][2] = Cu[r0 * SH + kb + m + 4];
                a[mg][3] = Cu[(r0 + 8) * SH + kb + m + 4];
            }
            u32 b[8][2];
            #pragma unroll
            for (int j = 0; j < 8; ++j) {
                int n = 64 * ch + 8 * j + q;
                b[j][0] = B1[n * SH + kb + m];
                b[j][1] = B1[n * SH + kb + m + 4];
            }
            #pragma unroll
            for (int mg = 0; mg < 2; ++mg)
                #pragma unroll
                for (int j = 0; j < 8; ++j) mma_tf32(acc[mg][j], a[mg], b[j]);
        }
        __syncthreads();   // all C reads done — overlay H onto Cs

        #pragma unroll
        for (int mg = 0; mg < 2; ++mg) {
            int r0 = 32 * rg + 16 * mg + q;
            #pragma unroll
            for (int j = 0; j < 8; ++j) {
                int col = 64 * ch + 8 * j + 2 * m;
                float bj0 = b1s[col], bj1 = b1s[col + 1];
                u32* p0 = (u32*)(Cs + r0 * SH + col);
                u32* p1 = (u32*)(Cs + (r0 + 8) * SH + col);
                p0[0] = to_tf32(fmaxf(acc[mg][j][0] + bj0, 0.f));
                p0[1] = to_tf32(fmaxf(acc[mg][j][1] + bj1, 0.f));
                p1[0] = to_tf32(fmaxf(acc[mg][j][2] + bj0, 0.f));
                p1[1] = to_tf32(fmaxf(acc[mg][j][3] + bj1, 0.f));
            }
        }
        __syncthreads();

        // GEMM2: D = H @ W2n (K=128)
        #pragma unroll
        for (int mg = 0; mg < 2; ++mg)
            #pragma unroll
            for (int j = 0; j < 8; ++j)
                #pragma unroll
                for (int c = 0; c < 4; ++c) acc[mg][j][c] = 0.f;

        #pragma unroll 2
        for (int kk = 0; kk < 16; ++kk) {
            int kb = kk * 8;
            u32 a[2][4];
            #pragma unroll
            for (int mg = 0; mg < 2; ++mg) {
                int r0 = 32 * rg + 16 * mg + q;
                a[mg][0] = Cu[r0 * SH + kb + m];
                a[mg][1] = Cu[(r0 + 8) * SH + kb + m];
                a[mg][2] = Cu[r0 * SH + kb + m + 4];
                a[mg][3] = Cu[(r0 + 8) * SH + kb + m + 4];
            }
            u32 b[8][2];
            #pragma unroll
            for (int j = 0; j < 8; ++j) {
                int n = 64 * ch + 8 * j + q;
                b[j][0] = B2[n * SH + kb + m];
                b[j][1] = B2[n * SH + kb + m + 4];
            }
            #pragma unroll
            for (int mg = 0; mg < 2; ++mg)
                #pragma unroll
                for (int j = 0; j < 8; ++j) mma_tf32(acc[mg][j], a[mg], b[j]);
        }
        __syncthreads();   // all H reads done — overlay staging

        // Stage o_pre = acc + b2  (x residual added in the passes below)
        #pragma unroll
        for (int mg = 0; mg < 2; ++mg) {
            int r0 = 32 * rg + 16 * mg + q;
            #pragma unroll
            for (int j = 0; j < 8; ++j) {
                int col = 64 * ch + 8 * j + 2 * m;
                float bj0 = b2s[col], bj1 = b2s[col + 1];
                Cs[r0 * SH + col]           = acc[mg][j][0] + bj0;
                Cs[r0 * SH + col + 1]       = acc[mg][j][1] + bj1;
                Cs[(r0 + 8) * SH + col]     = acc[mg][j][2] + bj0;
                Cs[(r0 + 8) * SH + col + 1] = acc[mg][j][3] + bj1;
            }
        }
        __syncthreads();

        // Pass 1: per-row sum of squares (2 threads per row)
        {
            int row = tid >> 1, half = tid & 1;
            int nn = n0 + row; int nc = (nn < NN) ? nn : NN - 1;
            float ss = 0.f;
            #pragma unroll
            for (int c4 = 0; c4 < 16; ++c4) {
                int col = half * 64 + c4 * 4;
                float4 mv = *(float4*)(Cs + row * SH + col);
                float4 xv = *(const float4*)(x + (size_t)nc * DIM + col);
                float a0 = mv.x + xv.x, a1 = mv.y + xv.y;
                float a2 = mv.z + xv.z, a3 = mv.w + xv.w;
                ss += a0 * a0 + a1 * a1 + a2 * a2 + a3 * a3;
            }
            ssb[tid] = ss;
        }
        __syncthreads();

        // Pass 2: scale + rms weight, coalesced store
        #pragma unroll
        for (int it = 0; it < 16; ++it) {
            int idx = tid + it * 256;
            int row = idx >> 5, c4 = idx & 31;
            int nn = n0 + row;
            if (nn < NN) {
                float tot = ssb[2 * row] + ssb[2 * row + 1];
                float sc = rsqrtf(tot * (1.f / 128.f) + RMS_EPS);
                float4 mv = *(float4*)(Cs + row * SH + c4 * 4);
                float4 xv = *(const float4*)(x + (size_t)nn * DIM + c4 * 4);
                float4 rw = *(float4*)(rws + c4 * 4);
                float4 o = make_float4((mv.x + xv.x) * sc * rw.x,
                                       (mv.y + xv.y) * sc * rw.y,
                                       (mv.z + xv.z) * sc * rw.z,
                                       (mv.w + xv.w) * sc * rw.w);
                *(float4*)(out + (size_t)nn * DIM + c4 * 4) = o;
            }
        }
    }
}

// ---------------- launch ----------------
extern "C" void kernel_launch(void* const* d_in, const int* in_sizes, int n_in,
                              void* d_out, int out_size)
{
    const float* x    = (const float*)d_in[0];
    const int*   eidx = (const int*)  d_in[1];
    const float* attr = (const float*)d_in[2];
    const float* b1n  = (const float*)d_in[4];
    const float* b2n  = (const float*)d_in[6];
    const float* W1n  = (const float*)d_in[3];
    const float* W2n  = (const float*)d_in[5];
    const float* W1e  = (const float*)d_in[7];
    const float* b1e  = (const float*)d_in[8];
    const float* W2e  = (const float*)d_in[9];
    const float* b2e  = (const float*)d_in[10];
    const float* geps = (const float*)d_in[11];
    const float* rmsw = (const float*)d_in[12];
    float* out = (float*)d_out;

    cudaFuncSetAttribute(k_edge, cudaFuncAttributeMaxDynamicSharedMemorySize, SME_EDGE);
    cudaFuncSetAttribute(k_node, cudaFuncAttributeMaxDynamicSharedMemorySize, SME_NODE);

    k_zero<<<(NN * DIM / 4 + 255) / 256, 256>>>();
    k_deg<<<(NE + 255) / 256, 256>>>(eidx + NE);
    k_inv<<<(NN + 255) / 256, 256>>>();
    k_prep<<<224, 256>>>(W1e, W2e, W1n, W2n);
    k_edge<<<148, 256, SME_EDGE>>>(x, eidx, attr, b1e, b2e);
    k_node<<<148, 256, SME_NODE>>>(x, b1n, b2n, geps, rmsw, out);
}